// round 9
// baseline (speedup 1.0000x reference)
#include <cuda_runtime.h>
#include <cuda_fp16.h>
#include <cstdint>
#include <math_constants.h>

// ============================================================================
// QKV_Attention via mma.sync m16n8k16 fp16 (f32 acc) + ldmatrix.
// Round 9: cp.async.bulk (UBLKCP) row copies + mbarrier complete_tx replace
// per-16B LDGSTS (8x fewer LSU issues). 144B-pitch rows (conflict-free LDSM,
// no swizzle needed). CTA 128x128, warp 64x32, BK=64, 3 stages, 2 CTA/SM.
// ============================================================================

#define NTHREADS 256
#define BK 64
#define PITCH 144                    // bytes per smem row (128 data + 16 pad)
#define ATILEB (128*PITCH)           // 18432
#define STAGEB (2*ATILEB)            // 36864 (A + B)
#define NSTAGE 3
#define DSMEMB (NSTAGE*STAGEB)       // 110592
#define TXBYTES 32768                // data bytes delivered per stage (2 tiles)

__device__ __half g_qh [4096UL*4096UL];      // 32 MB
__device__ __half g_xh [4UL*1024UL*512UL];   //  4 MB
__device__ __half g_wh [4096UL*512UL];       //  4 MB
__device__ __half g_xth[4UL*512UL*1024UL];   //  4 MB
__device__ __half g_ph [32768UL*1024UL];     // 64 MB

// ---------------------------------------------------------------- helpers
__device__ __forceinline__ uint32_t smem_u32(const void* p) {
    uint32_t a;
    asm("{ .reg .u64 t; cvta.to.shared.u64 t, %1; cvt.u32.u64 %0, t; }"
        : "=r"(a) : "l"(p));
    return a;
}
#define MBAR_INIT(a, c) \
    asm volatile("mbarrier.init.shared.b64 [%0], %1;" :: "r"(a), "r"(c) : "memory")
#define MBAR_EXPECT(a, b) \
    asm volatile("mbarrier.arrive.expect_tx.shared.b64 _, [%0], %1;" :: "r"(a), "r"(b) : "memory")
#define MBAR_WAIT(a, ph) do { \
    uint32_t _m = (a); uint32_t _p = (ph); uint32_t _d; \
    asm volatile("{ .reg .pred p; mbarrier.try_wait.parity.acquire.cta.shared::cta.b64 p, [%1], %2; selp.b32 %0, 1, 0, p; }" \
        : "=r"(_d) : "r"(_m), "r"(_p) : "memory"); \
    if (!_d) { \
        asm volatile("{ .reg .pred P1; WL_%=: mbarrier.try_wait.parity.acquire.cta.shared::cta.b64 P1, [%0], %1, 0x989680; @P1 bra.uni WD_%=; bra.uni WL_%=; WD_%=: }" \
            :: "r"(_m), "r"(_p) : "memory"); \
    } } while (0)

// one 128-byte row: global -> shared, completion via mbarrier complete_tx
#define BULK128(dst, src, mbar) \
    asm volatile("cp.async.bulk.shared::cluster.global.mbarrier::complete_tx::bytes [%0], [%1], 128, [%2];" \
        :: "r"(dst), "l"(src), "r"(mbar) : "memory")

#define LDSM4(r, a) \
    asm volatile("ldmatrix.sync.aligned.m8n8.x4.shared.b16 {%0,%1,%2,%3}, [%4];" \
        : "=r"((r)[0]), "=r"((r)[1]), "=r"((r)[2]), "=r"((r)[3]) : "r"(a))

__device__ __forceinline__ void mma_f16(float c[4], const uint32_t a[4],
                                        uint32_t b0, uint32_t b1) {
    asm volatile(
        "mma.sync.aligned.m16n8k16.row.col.f32.f16.f16.f32 "
        "{%0,%1,%2,%3}, {%4,%5,%6,%7}, {%8,%9}, {%0,%1,%2,%3};"
        : "+f"(c[0]), "+f"(c[1]), "+f"(c[2]), "+f"(c[3])
        : "r"(a[0]), "r"(a[1]), "r"(a[2]), "r"(a[3]), "r"(b0), "r"(b1));
}

// ============================================================================
// NT GEMM (fp16 in, f32 acc): C[m,n] = alpha * sum_k A[m,k]*B[n,k]
// CTA tile 128x128, 8 warps (2x4), warp tile 64x32, BK=64, 3-stage bulk-copy
// pipeline. Each thread issues exactly ONE 128B bulk copy per stage.
// ============================================================================
__global__ void __launch_bounds__(NTHREADS, 2)
gemm_h(const __half* __restrict__ A, int lda, long sAb, long sAk,
       const __half* __restrict__ B, int ldb, long sBb, long sBk,
       void* __restrict__ Cv, int ldc, long sCb, long sCk,
       int Kdim, float alpha, int Kcnt, int halfOut)
{
    extern __shared__ __half smh[];
    __shared__ __align__(8) uint64_t s_mbar[NSTAGE];
    const uint32_t smb = smem_u32(smh);
    const uint32_t mb0 = smem_u32(&s_mbar[0]);

    const int tid  = threadIdx.x;
    const int wid  = tid >> 5;
    const int lane = tid & 31;
    const int gid  = lane >> 2;
    const int tg   = lane & 3;
    const int warpMoff = (wid >> 2) * 64;   // 0,64
    const int warpNoff = (wid & 3) * 32;    // 0..96

    const int z  = blockIdx.z;
    const int zb = z / Kcnt;
    const int zk = z - zb * Kcnt;
    const __half* Ab = A + (size_t)zb * sAb + (size_t)zk * sAk + (size_t)(blockIdx.y * 128) * lda;
    const __half* Bb = B + (size_t)zb * sBb + (size_t)zk * sBk + (size_t)(blockIdx.x * 128) * ldb;
    const size_t cOff = (size_t)zb * sCb + (size_t)zk * sCk
                      + (size_t)(blockIdx.y * 128) * ldc + (size_t)(blockIdx.x * 128);

    const int numK = Kdim >> 6;     // always >= 8 here

    // this thread's one row per stage: A rows for tid<128, B rows otherwise
    const int myRow = tid & 127;
    const int myIsB = tid >> 7;
    const __half* mySrcBase = (myIsB ? Bb : Ab) + (size_t)myRow * (myIsB ? ldb : lda);
    const uint32_t myDstOff = (uint32_t)(myIsB ? ATILEB : 0) + (uint32_t)myRow * PITCH;

    float c[4][4][4];
#pragma unroll
    for (int i = 0; i < 4; i++)
#pragma unroll
        for (int j = 0; j < 4; j++)
#pragma unroll
            for (int r = 0; r < 4; r++) c[i][j][r] = 0.0f;

    // fixed per-lane ldmatrix row components
    const int rlA = lane & 15;
    const int hiA = lane >> 4;
    const int rlB = ((lane >> 4) << 3) + (lane & 7);
    const int hiB = (lane >> 3) & 1;

    // ---- init barriers + prologue expects (race-free: barriers between)
    if (tid == 0) {
#pragma unroll
        for (int s = 0; s < NSTAGE; s++) MBAR_INIT(mb0 + 8 * s, 1);
    }
    __syncthreads();
    if (tid == 0) {
#pragma unroll
        for (int s = 0; s < NSTAGE; s++) MBAR_EXPECT(mb0 + 8 * s, TXBYTES);
    }
    __syncthreads();

    // issue stages 0 and 1 (one bulk copy per thread per stage)
    BULK128(smb + myDstOff, mySrcBase, mb0);
    BULK128(smb + STAGEB + myDstOff, mySrcBase + BK, mb0 + 8);

    int buf = 0;
    for (int kt = 0; kt < numK; kt++) {
        MBAR_WAIT(mb0 + 8 * buf, (uint32_t)((kt / NSTAGE) & 1));
        __syncthreads();   // all warps done with compute kt-1 (buf reuse safety)

        // expect for stage kt+3 (same barrier slot as buf, next phase);
        // its bulk issues happen next iteration -> no expect/complete race
        if (tid == 0 && kt + NSTAGE < numK)
            MBAR_EXPECT(mb0 + 8 * buf, TXBYTES);

        // issue loads for stage kt+2
        const int nk = kt + 2;
        if (nk < numK) {
            int nbuf = buf + 2; if (nbuf >= NSTAGE) nbuf -= NSTAGE;
            BULK128(smb + nbuf * STAGEB + myDstOff, mySrcBase + nk * BK, mb0 + 8 * nbuf);
        }

        const uint32_t At = smb + buf * STAGEB;
        const uint32_t Bt = At + ATILEB;

#pragma unroll
        for (int kk = 0; kk < 4; kk++) {
            uint32_t a[4][4], bb[2][4];
            const int cA = kk * 2 + hiA;
            const int cB = kk * 2 + hiB;
#pragma unroll
            for (int i = 0; i < 4; i++) {
                const int row = warpMoff + i * 16 + rlA;
                uint32_t ad = At + (uint32_t)row * PITCH + (uint32_t)(cA << 4);
                LDSM4(a[i], ad);
            }
#pragma unroll
            for (int j = 0; j < 2; j++) {
                const int row = warpNoff + j * 16 + rlB;
                uint32_t bd = Bt + (uint32_t)row * PITCH + (uint32_t)(cB << 4);
                LDSM4(bb[j], bd);
            }
#pragma unroll
            for (int i = 0; i < 4; i++)
#pragma unroll
                for (int jj = 0; jj < 4; jj++)
                    mma_f16(c[i][jj], a[i], bb[jj >> 1][(jj & 1) * 2],
                                             bb[jj >> 1][(jj & 1) * 2 + 1]);
        }

        if (++buf == NSTAGE) buf = 0;
    }

    // ---- epilogue
    if (halfOut) {
        __half* Cb = (__half*)Cv + cOff;
#pragma unroll
        for (int i = 0; i < 4; i++) {
            const int r0 = warpMoff + i * 16 + gid;
#pragma unroll
            for (int jj = 0; jj < 4; jj++) {
                const int cc = warpNoff + jj * 8 + tg * 2;
                *(__half2*)(Cb + (size_t)r0 * ldc + cc) =
                    __floats2half2_rn(alpha * c[i][jj][0], alpha * c[i][jj][1]);
                *(__half2*)(Cb + (size_t)(r0 + 8) * ldc + cc) =
                    __floats2half2_rn(alpha * c[i][jj][2], alpha * c[i][jj][3]);
            }
        }
    } else {
        float* Cb = (float*)Cv + cOff;
#pragma unroll
        for (int i = 0; i < 4; i++) {
            const int r0 = warpMoff + i * 16 + gid;
#pragma unroll
            for (int jj = 0; jj < 4; jj++) {
                const int cc = warpNoff + jj * 8 + tg * 2;
                float2 v0, v1;
                v0.x = alpha * c[i][jj][0]; v0.y = alpha * c[i][jj][1];
                v1.x = alpha * c[i][jj][2]; v1.y = alpha * c[i][jj][3];
                *(float2*)(Cb + (size_t)r0 * ldc + cc)       = v0;
                *(float2*)(Cb + (size_t)(r0 + 8) * ldc + cc) = v1;
            }
        }
    }
}

// ============================================================================
// prep: f32 -> fp16
// ============================================================================
__global__ void cvt_h(const float* __restrict__ in, __half* __restrict__ out, int n4)
{
    int i = blockIdx.x * blockDim.x + threadIdx.x;
    if (i >= n4) return;
    float4 v = ((const float4*)in)[i];
    ((__half2*)out)[2 * i]     = __floats2half2_rn(v.x, v.y);
    ((__half2*)out)[2 * i + 1] = __floats2half2_rn(v.z, v.w);
}

// transpose xsa (b,1024,512) f32 -> g_xth (b,512,1024) fp16
__global__ void transpose_h(const float* __restrict__ in, __half* __restrict__ out)
{
    __shared__ float t[32][33];
    const int b = blockIdx.z;
    const int l0 = blockIdx.x * 32, e0 = blockIdx.y * 32;
    in  += (size_t)b * 524288;
    out += (size_t)b * 524288;
    const int x = threadIdx.x, y = threadIdx.y;  // 32 x 8
#pragma unroll
    for (int i = 0; i < 32; i += 8)
        t[y + i][x] = in[(size_t)(l0 + y + i) * 512 + e0 + x];
    __syncthreads();
#pragma unroll
    for (int i = 0; i < 32; i += 8)
        out[(size_t)(e0 + y + i) * 1024 + l0 + x] = __float2half_rn(t[x][y + i]);
}

// ============================================================================
// softmax rows of 1024, in place (f32); also writes fp16 copy to ph
// ============================================================================
__global__ void softmax_rows_kernel(float* __restrict__ p, __half* __restrict__ ph)
{
    __shared__ float red[32];
    const size_t roff = (size_t)blockIdx.x * 1024;
    float* row = p + roff;
    const int t = threadIdx.x;

    float4 v = ((const float4*)row)[t];

    float m = fmaxf(fmaxf(v.x, v.y), fmaxf(v.z, v.w));
#pragma unroll
    for (int o = 16; o; o >>= 1) m = fmaxf(m, __shfl_xor_sync(0xffffffffu, m, o));
    if ((t & 31) == 0) red[t >> 5] = m;
    __syncthreads();
    if (t < 32) {
        float mm = (t < 8) ? red[t] : -CUDART_INF_F;
#pragma unroll
        for (int o = 4; o; o >>= 1) mm = fmaxf(mm, __shfl_xor_sync(0xffffffffu, mm, o));
        if (t == 0) red[0] = mm;
    }
    __syncthreads();
    m = red[0];
    __syncthreads();

    v.x = __expf(v.x - m); v.y = __expf(v.y - m);
    v.z = __expf(v.z - m); v.w = __expf(v.w - m);

    float s = v.x + v.y + v.z + v.w;
#pragma unroll
    for (int o = 16; o; o >>= 1) s += __shfl_xor_sync(0xffffffffu, s, o);
    if ((t & 31) == 0) red[t >> 5] = s;
    __syncthreads();
    if (t < 32) {
        float ss = (t < 8) ? red[t] : 0.0f;
#pragma unroll
        for (int o = 4; o; o >>= 1) ss += __shfl_xor_sync(0xffffffffu, ss, o);
        if (t == 0) red[0] = ss;
    }
    __syncthreads();
    const float inv = 1.0f / red[0];

    v.x *= inv; v.y *= inv; v.z *= inv; v.w *= inv;
    ((float4*)row)[t] = v;

    __half2* pp = (__half2*)(ph + roff);
    pp[2 * t]     = __floats2half2_rn(v.x, v.y);
    pp[2 * t + 1] = __floats2half2_rn(v.z, v.w);
}

// ============================================================================
extern "C" void kernel_launch(void* const* d_in, const int* in_sizes, int n_in,
                              void* d_out, int out_size)
{
    (void)in_sizes; (void)n_in; (void)out_size;
    const float* xsa = (const float*)d_in[0];   // (4,1024,512)
    const float* Wq  = (const float*)d_in[1];   // (4096,512)
    float* out  = (float*)d_out;
    float* xid  = out;                          // 16777216 floats
    float* pijk = out + 16777216UL;             // 33554432 floats

    __half *qh, *xh, *wh, *xth, *ph;
    cudaGetSymbolAddress((void**)&qh,  g_qh);
    cudaGetSymbolAddress((void**)&xh,  g_xh);
    cudaGetSymbolAddress((void**)&wh,  g_wh);
    cudaGetSymbolAddress((void**)&xth, g_xth);
    cudaGetSymbolAddress((void**)&ph,  g_ph);

    cudaFuncSetAttribute(gemm_h, cudaFuncAttributeMaxDynamicSharedMemorySize, DSMEMB);

    const float inv_sqrt_e = 0.044194173824159216f;  // 1/sqrt(512)

    // prep
    cvt_h<<<2048, 256>>>(xsa, xh, 524288);
    cvt_h<<<2048, 256>>>(Wq,  wh, 524288);
    transpose_h<<<dim3(32, 16, 4), dim3(32, 8)>>>(xsa, xth);

    // K1: q = xh @ wh^T   M=4096 N=4096 K=512, fp16 out
    gemm_h<<<dim3(32, 32, 1), NTHREADS, DSMEMB>>>(
        xh, 512, 0, 0,
        wh, 512, 0, 0,
        qh, 4096, 0, 0,
        512, 1.0f, 1, 1);

    // K2: logits = qh_bk @ xh_b^T / sqrt(E)   M=1024 N=1024 K=512, 32 batches
    gemm_h<<<dim3(8, 8, 32), NTHREADS, DSMEMB>>>(
        qh, 4096, 4194304L, 512L,
        xh, 512,  524288L,  0L,
        pijk, 8192, 8388608L, 1024L,
        512, inv_sqrt_e, 8, 0);

    // K3: softmax -> pijk f32 (output) + ph fp16 (K4 operand)
    softmax_rows_kernel<<<32768, 256>>>(pijk, ph);

    // K4: y = ph_bk @ xth_b^T   M=1024 N=512 K=1024, 32 batches
    // ph layout (b,l,k,m): row stride 8192, k stride 1024
    gemm_h<<<dim3(4, 8, 32), NTHREADS, DSMEMB>>>(
        ph,  8192, 8388608L, 1024L,
        xth, 1024, 524288L,  0L,
        xid, 4096, 4194304L, 512L,
        1024, 1.0f, 8, 0);
}

// round 11
// speedup vs baseline: 1.2218x; 1.2218x over previous
#include <cuda_runtime.h>
#include <cuda_fp16.h>
#include <cstdint>
#include <math_constants.h>

// ============================================================================
// QKV_Attention via mma.sync m16n8k16 fp16 (f32 acc) + ldmatrix.
// Round 11: R6 champion GEMM. Overlap DAG with NO created streams (uses
// cudaStreamPerThread; events created+destroyed in-call -> no leak):
//   - transpose forked alongside cvt + K1
//   - K2 whole (2048 CTAs, minimal wave tail)
//   - softmax per batch on side stream; K4 per batch (256 CTAs = exactly one
//     wave, tail-free split) gated per batch -> softmax(1..3) hides under K4.
// ============================================================================

#define NTHREADS 256
#define BK 64
#define TILEB 16384                 // 128 rows x 128B
#define STAGEB (2*TILEB)            // A + B
#define NSTAGE 3
#define DSMEMB (NSTAGE*STAGEB)      // 98304

__device__ __half g_qh [4096UL*4096UL];      // 32 MB
__device__ __half g_xh [4UL*1024UL*512UL];   //  4 MB
__device__ __half g_wh [4096UL*512UL];       //  4 MB
__device__ __half g_xth[4UL*512UL*1024UL];   //  4 MB
__device__ __half g_ph [32768UL*1024UL];     // 64 MB

// ---------------------------------------------------------------- helpers
__device__ __forceinline__ uint32_t smem_u32(const void* p) {
    uint32_t a;
    asm("{ .reg .u64 t; cvta.to.shared.u64 t, %1; cvt.u32.u64 %0, t; }"
        : "=r"(a) : "l"(p));
    return a;
}
#define CP16(d, s) \
    asm volatile("cp.async.cg.shared.global [%0], [%1], 16;" :: "r"(d), "l"(s))
#define CP_COMMIT() asm volatile("cp.async.commit_group;" ::: "memory")
#define CP_WAIT1()  asm volatile("cp.async.wait_group 1;" ::: "memory")

#define LDSM4(r, a) \
    asm volatile("ldmatrix.sync.aligned.m8n8.x4.shared.b16 {%0,%1,%2,%3}, [%4];" \
        : "=r"((r)[0]), "=r"((r)[1]), "=r"((r)[2]), "=r"((r)[3]) : "r"(a))

__device__ __forceinline__ void mma_f16(float c[4], const uint32_t a[4],
                                        uint32_t b0, uint32_t b1) {
    asm volatile(
        "mma.sync.aligned.m16n8k16.row.col.f32.f16.f16.f32 "
        "{%0,%1,%2,%3}, {%4,%5,%6,%7}, {%8,%9}, {%0,%1,%2,%3};"
        : "+f"(c[0]), "+f"(c[1]), "+f"(c[2]), "+f"(c[3])
        : "r"(a[0]), "r"(a[1]), "r"(a[2]), "r"(a[3]), "r"(b0), "r"(b1));
}

// load 128 rows x 64 fp16 (row stride ld elems) into XOR-swizzled smem tile
__device__ __forceinline__ void load_tile_h(uint32_t dst, const __half* g, int ld, int tid) {
#pragma unroll
    for (int i = 0; i < 4; i++) {
        int idx = tid + i * NTHREADS;
        int row = idx >> 3;
        int c   = idx & 7;
        uint32_t off = (uint32_t)(row << 7) | (uint32_t)(((c ^ (row & 7)) << 4));
        CP16(dst + off, g + (size_t)row * ld + (c << 3));
    }
}

// ============================================================================
// NT GEMM (fp16 in, f32 acc): C[m,n] = alpha * sum_k A[m,k]*B[n,k]
// CTA tile 128x128, 8 warps (2x4), warp tile 64x32, BK=64, 3 stages.
// (byte-identical to round-6 champion)
// ============================================================================
__global__ void __launch_bounds__(NTHREADS, 2)
gemm_h(const __half* __restrict__ A, int lda, long sAb, long sAk,
       const __half* __restrict__ B, int ldb, long sBb, long sBk,
       void* __restrict__ Cv, int ldc, long sCb, long sCk,
       int Kdim, float alpha, int Kcnt, int halfOut)
{
    extern __shared__ __half smh[];
    const uint32_t smb = smem_u32(smh);

    const int tid  = threadIdx.x;
    const int wid  = tid >> 5;
    const int lane = tid & 31;
    const int gid  = lane >> 2;
    const int tg   = lane & 3;
    const int warpMoff = (wid >> 2) * 64;
    const int warpNoff = (wid & 3) * 32;

    const int z  = blockIdx.z;
    const int zb = z / Kcnt;
    const int zk = z - zb * Kcnt;
    const __half* Ab = A + (size_t)zb * sAb + (size_t)zk * sAk + (size_t)(blockIdx.y * 128) * lda;
    const __half* Bb = B + (size_t)zb * sBb + (size_t)zk * sBk + (size_t)(blockIdx.x * 128) * ldb;
    const size_t cOff = (size_t)zb * sCb + (size_t)zk * sCk
                      + (size_t)(blockIdx.y * 128) * ldc + (size_t)(blockIdx.x * 128);

    const int numK = Kdim >> 6;

    float c[4][4][4];
#pragma unroll
    for (int i = 0; i < 4; i++)
#pragma unroll
        for (int j = 0; j < 4; j++)
#pragma unroll
            for (int r = 0; r < 4; r++) c[i][j][r] = 0.0f;

    const int rlA = lane & 15;
    const int hiA = lane >> 4;
    const int rlB = ((lane >> 4) << 3) + (lane & 7);
    const int hiB = (lane >> 3) & 1;

    load_tile_h(smb,          Ab, lda, tid);
    load_tile_h(smb + TILEB,  Bb, ldb, tid);
    CP_COMMIT();
    if (numK > 1) {
        load_tile_h(smb + STAGEB,         Ab + BK, lda, tid);
        load_tile_h(smb + STAGEB + TILEB, Bb + BK, ldb, tid);
    }
    CP_COMMIT();

    int buf = 0;
    for (int kt = 0; kt < numK; kt++) {
        CP_WAIT1();
        __syncthreads();

        const int nk = kt + 2;
        if (nk < numK) {
            int nbuf = buf + 2; if (nbuf >= NSTAGE) nbuf -= NSTAGE;
            const uint32_t nbb = smb + nbuf * STAGEB;
            load_tile_h(nbb,         Ab + nk * BK, lda, tid);
            load_tile_h(nbb + TILEB, Bb + nk * BK, ldb, tid);
        }
        CP_COMMIT();

        const uint32_t At = smb + buf * STAGEB;
        const uint32_t Bt = At + TILEB;

#pragma unroll
        for (int kk = 0; kk < 4; kk++) {
            uint32_t a[4][4], bb[2][4];
            const int cA = kk * 2 + hiA;
            const int cB = kk * 2 + hiB;
#pragma unroll
            for (int i = 0; i < 4; i++) {
                const int row = warpMoff + i * 16 + rlA;
                uint32_t ad = At + ((uint32_t)row << 7)
                            + (uint32_t)(((cA ^ (row & 7)) << 4));
                LDSM4(a[i], ad);
            }
#pragma unroll
            for (int j = 0; j < 2; j++) {
                const int row = warpNoff + j * 16 + rlB;
                uint32_t bd = Bt + ((uint32_t)row << 7)
                            + (uint32_t)(((cB ^ (row & 7)) << 4));
                LDSM4(bb[j], bd);
            }
#pragma unroll
            for (int i = 0; i < 4; i++)
#pragma unroll
                for (int jj = 0; jj < 4; jj++)
                    mma_f16(c[i][jj], a[i], bb[jj >> 1][(jj & 1) * 2],
                                             bb[jj >> 1][(jj & 1) * 2 + 1]);
        }

        if (++buf == NSTAGE) buf = 0;
    }

    if (halfOut) {
        __half* Cb = (__half*)Cv + cOff;
#pragma unroll
        for (int i = 0; i < 4; i++) {
            const int r0 = warpMoff + i * 16 + gid;
#pragma unroll
            for (int jj = 0; jj < 4; jj++) {
                const int cc = warpNoff + jj * 8 + tg * 2;
                *(__half2*)(Cb + (size_t)r0 * ldc + cc) =
                    __floats2half2_rn(alpha * c[i][jj][0], alpha * c[i][jj][1]);
                *(__half2*)(Cb + (size_t)(r0 + 8) * ldc + cc) =
                    __floats2half2_rn(alpha * c[i][jj][2], alpha * c[i][jj][3]);
            }
        }
    } else {
        float* Cb = (float*)Cv + cOff;
#pragma unroll
        for (int i = 0; i < 4; i++) {
            const int r0 = warpMoff + i * 16 + gid;
#pragma unroll
            for (int jj = 0; jj < 4; jj++) {
                const int cc = warpNoff + jj * 8 + tg * 2;
                float2 v0, v1;
                v0.x = alpha * c[i][jj][0]; v0.y = alpha * c[i][jj][1];
                v1.x = alpha * c[i][jj][2]; v1.y = alpha * c[i][jj][3];
                *(float2*)(Cb + (size_t)r0 * ldc + cc)       = v0;
                *(float2*)(Cb + (size_t)(r0 + 8) * ldc + cc) = v1;
            }
        }
    }
}

// ============================================================================
// merged prep: f32 -> fp16 for xsa and Wq
// ============================================================================
__global__ void cvt_both(const float* __restrict__ xsa, const float* __restrict__ Wq,
                         __half* __restrict__ xh, __half* __restrict__ wh)
{
    int i = blockIdx.x * blockDim.x + threadIdx.x;   // 0..1048575
    const float* in; __half* out; int j;
    if (i < 524288) { in = xsa; out = xh; j = i; }
    else            { in = Wq;  out = wh; j = i - 524288; }
    float4 v = ((const float4*)in)[j];
    ((__half2*)out)[2 * j]     = __floats2half2_rn(v.x, v.y);
    ((__half2*)out)[2 * j + 1] = __floats2half2_rn(v.z, v.w);
}

// transpose xsa (b,1024,512) f32 -> g_xth (b,512,1024) fp16
__global__ void transpose_h(const float* __restrict__ in, __half* __restrict__ out)
{
    __shared__ float t[32][33];
    const int b = blockIdx.z;
    const int l0 = blockIdx.x * 32, e0 = blockIdx.y * 32;
    in  += (size_t)b * 524288;
    out += (size_t)b * 524288;
    const int x = threadIdx.x, y = threadIdx.y;
#pragma unroll
    for (int i = 0; i < 32; i += 8)
        t[y + i][x] = in[(size_t)(l0 + y + i) * 512 + e0 + x];
    __syncthreads();
#pragma unroll
    for (int i = 0; i < 32; i += 8)
        out[(size_t)(e0 + y + i) * 1024 + l0 + x] = __float2half_rn(t[x][y + i]);
}

// ============================================================================
// softmax rows of 1024, in place (f32); also writes fp16 copy to ph
// ============================================================================
__global__ void softmax_rows_kernel(float* __restrict__ p, __half* __restrict__ ph)
{
    __shared__ float red[32];
    const size_t roff = (size_t)blockIdx.x * 1024;
    float* row = p + roff;
    const int t = threadIdx.x;

    float4 v = ((const float4*)row)[t];

    float m = fmaxf(fmaxf(v.x, v.y), fmaxf(v.z, v.w));
#pragma unroll
    for (int o = 16; o; o >>= 1) m = fmaxf(m, __shfl_xor_sync(0xffffffffu, m, o));
    if ((t & 31) == 0) red[t >> 5] = m;
    __syncthreads();
    if (t < 32) {
        float mm = (t < 8) ? red[t] : -CUDART_INF_F;
#pragma unroll
        for (int o = 4; o; o >>= 1) mm = fmaxf(mm, __shfl_xor_sync(0xffffffffu, mm, o));
        if (t == 0) red[0] = mm;
    }
    __syncthreads();
    m = red[0];
    __syncthreads();

    v.x = __expf(v.x - m); v.y = __expf(v.y - m);
    v.z = __expf(v.z - m); v.w = __expf(v.w - m);

    float s = v.x + v.y + v.z + v.w;
#pragma unroll
    for (int o = 16; o; o >>= 1) s += __shfl_xor_sync(0xffffffffu, s, o);
    if ((t & 31) == 0) red[t >> 5] = s;
    __syncthreads();
    if (t < 32) {
        float ss = (t < 8) ? red[t] : 0.0f;
#pragma unroll
        for (int o = 4; o; o >>= 1) ss += __shfl_xor_sync(0xffffffffu, ss, o);
        if (t == 0) red[0] = ss;
    }
    __syncthreads();
    const float inv = 1.0f / red[0];

    v.x *= inv; v.y *= inv; v.z *= inv; v.w *= inv;
    ((float4*)row)[t] = v;

    __half2* pp = (__half2*)(ph + roff);
    pp[2 * t]     = __floats2half2_rn(v.x, v.y);
    pp[2 * t + 1] = __floats2half2_rn(v.z, v.w);
}

// ============================================================================
extern "C" void kernel_launch(void* const* d_in, const int* in_sizes, int n_in,
                              void* d_out, int out_size)
{
    (void)in_sizes; (void)n_in; (void)out_size;
    const float* xsa = (const float*)d_in[0];
    const float* Wq  = (const float*)d_in[1];
    float* out  = (float*)d_out;
    float* xid  = out;
    float* pijk = out + 16777216UL;

    __half *qh, *xh, *wh, *xth, *ph;
    cudaGetSymbolAddress((void**)&qh,  g_qh);
    cudaGetSymbolAddress((void**)&xh,  g_xh);
    cudaGetSymbolAddress((void**)&wh,  g_wh);
    cudaGetSymbolAddress((void**)&xth, g_xth);
    cudaGetSymbolAddress((void**)&ph,  g_ph);

    cudaFuncSetAttribute(gemm_h, cudaFuncAttributeMaxDynamicSharedMemorySize, DSMEMB);

    const float inv_sqrt_e = 0.044194173824159216f;

    // Side stream: the BUILT-IN per-thread stream (no create/destroy -> no
    // leak). Events are created and destroyed within this call; record/wait
    // become graph nodes at API-call time, so destroying afterward is safe.
    cudaStream_t side = cudaStreamPerThread;
    cudaEvent_t eFork, eT, e2, e3[4];
    cudaEventCreateWithFlags(&eFork, cudaEventDisableTiming);
    cudaEventCreateWithFlags(&eT,    cudaEventDisableTiming);
    cudaEventCreateWithFlags(&e2,    cudaEventDisableTiming);
    for (int b = 0; b < 4; b++)
        cudaEventCreateWithFlags(&e3[b], cudaEventDisableTiming);

    // fork: transpose (needed only by K4) overlaps cvt + K1
    cudaEventRecord(eFork, 0);
    cudaStreamWaitEvent(side, eFork, 0);
    transpose_h<<<dim3(32, 16, 4), dim3(32, 8), 0, side>>>(xsa, xth);
    cudaEventRecord(eT, side);

    // main: prep then K1
    cvt_both<<<4096, 256>>>(xsa, Wq, xh, wh);
    gemm_h<<<dim3(32, 32, 1), NTHREADS, DSMEMB>>>(
        xh, 512, 0, 0,
        wh, 512, 0, 0,
        qh, 4096, 0, 0,
        512, 1.0f, 1, 1);

    // K2 whole (2048 CTAs -> minimal wave tail)
    gemm_h<<<dim3(8, 8, 32), NTHREADS, DSMEMB>>>(
        qh, 4096, 4194304L, 512L,
        xh, 512,  524288L,  0L,
        pijk, 8192, 8388608L, 1024L,
        512, inv_sqrt_e, 8, 0);
    cudaEventRecord(e2, 0);

    // softmax per batch on the side stream
    cudaStreamWaitEvent(side, e2, 0);
    for (int b = 0; b < 4; b++) {
        softmax_rows_kernel<<<8192, 256, 0, side>>>(
            pijk + (size_t)b * 8388608UL, ph + (size_t)b * 8388608UL);
        cudaEventRecord(e3[b], side);
    }

    // K4 per batch (256 CTAs = one full wave each -> tail-free split);
    // K4(b) gated on softmax(b), so softmax(b+1..) overlaps K4(b)
    cudaStreamWaitEvent(0, eT, 0);
    for (int b = 0; b < 4; b++) {
        cudaStreamWaitEvent(0, e3[b], 0);
        gemm_h<<<dim3(4, 8, 8), NTHREADS, DSMEMB>>>(
            ph  + (size_t)b * 8388608UL, 8192, 0, 1024L,
            xth + (size_t)b * 524288UL,  1024, 0, 0L,
            xid + (size_t)b * 4194304UL, 4096, 0, 512L,
            1024, 1.0f, 8, 0);
    }

    // destroy events (handles no longer referenced by the capture)
    cudaEventDestroy(eFork);
    cudaEventDestroy(eT);
    cudaEventDestroy(e2);
    for (int b = 0; b < 4; b++) cudaEventDestroy(e3[b]);
}

// round 12
// speedup vs baseline: 1.3315x; 1.0897x over previous
#include <cuda_runtime.h>
#include <cuda_fp16.h>
#include <cstdint>
#include <math_constants.h>

// ============================================================================
// QKV_Attention via mma.sync m16n8k16 fp16 (f32 acc) + ldmatrix.
// Round 12: R6 champion GEMM + serial launch order (overlap abandoned:
// created streams leak; cudaStreamPerThread syncs with legacy stream).
// Trim: prep_x fuses xsa fp16-convert + transpose (one xsa read, one launch).
// ============================================================================

#define NTHREADS 256
#define BK 64
#define TILEB 16384                 // 128 rows x 128B
#define STAGEB (2*TILEB)            // A + B
#define NSTAGE 3
#define DSMEMB (NSTAGE*STAGEB)      // 98304

__device__ __half g_qh [4096UL*4096UL];      // 32 MB
__device__ __half g_xh [4UL*1024UL*512UL];   //  4 MB
__device__ __half g_wh [4096UL*512UL];       //  4 MB
__device__ __half g_xth[4UL*512UL*1024UL];   //  4 MB
__device__ __half g_ph [32768UL*1024UL];     // 64 MB

// ---------------------------------------------------------------- helpers
__device__ __forceinline__ uint32_t smem_u32(const void* p) {
    uint32_t a;
    asm("{ .reg .u64 t; cvta.to.shared.u64 t, %1; cvt.u32.u64 %0, t; }"
        : "=r"(a) : "l"(p));
    return a;
}
#define CP16(d, s) \
    asm volatile("cp.async.cg.shared.global [%0], [%1], 16;" :: "r"(d), "l"(s))
#define CP_COMMIT() asm volatile("cp.async.commit_group;" ::: "memory")
#define CP_WAIT1()  asm volatile("cp.async.wait_group 1;" ::: "memory")

#define LDSM4(r, a) \
    asm volatile("ldmatrix.sync.aligned.m8n8.x4.shared.b16 {%0,%1,%2,%3}, [%4];" \
        : "=r"((r)[0]), "=r"((r)[1]), "=r"((r)[2]), "=r"((r)[3]) : "r"(a))

__device__ __forceinline__ void mma_f16(float c[4], const uint32_t a[4],
                                        uint32_t b0, uint32_t b1) {
    asm volatile(
        "mma.sync.aligned.m16n8k16.row.col.f32.f16.f16.f32 "
        "{%0,%1,%2,%3}, {%4,%5,%6,%7}, {%8,%9}, {%0,%1,%2,%3};"
        : "+f"(c[0]), "+f"(c[1]), "+f"(c[2]), "+f"(c[3])
        : "r"(a[0]), "r"(a[1]), "r"(a[2]), "r"(a[3]), "r"(b0), "r"(b1));
}

// load 128 rows x 64 fp16 (row stride ld elems) into XOR-swizzled smem tile
__device__ __forceinline__ void load_tile_h(uint32_t dst, const __half* g, int ld, int tid) {
#pragma unroll
    for (int i = 0; i < 4; i++) {
        int idx = tid + i * NTHREADS;
        int row = idx >> 3;
        int c   = idx & 7;
        uint32_t off = (uint32_t)(row << 7) | (uint32_t)(((c ^ (row & 7)) << 4));
        CP16(dst + off, g + (size_t)row * ld + (c << 3));
    }
}

// ============================================================================
// NT GEMM (fp16 in, f32 acc): C[m,n] = alpha * sum_k A[m,k]*B[n,k]
// CTA tile 128x128, 8 warps (2x4), warp tile 64x32, BK=64, 3 stages.
// (byte-identical to round-6 champion)
// ============================================================================
__global__ void __launch_bounds__(NTHREADS, 2)
gemm_h(const __half* __restrict__ A, int lda, long sAb, long sAk,
       const __half* __restrict__ B, int ldb, long sBb, long sBk,
       void* __restrict__ Cv, int ldc, long sCb, long sCk,
       int Kdim, float alpha, int Kcnt, int halfOut)
{
    extern __shared__ __half smh[];
    const uint32_t smb = smem_u32(smh);

    const int tid  = threadIdx.x;
    const int wid  = tid >> 5;
    const int lane = tid & 31;
    const int gid  = lane >> 2;
    const int tg   = lane & 3;
    const int warpMoff = (wid >> 2) * 64;
    const int warpNoff = (wid & 3) * 32;

    const int z  = blockIdx.z;
    const int zb = z / Kcnt;
    const int zk = z - zb * Kcnt;
    const __half* Ab = A + (size_t)zb * sAb + (size_t)zk * sAk + (size_t)(blockIdx.y * 128) * lda;
    const __half* Bb = B + (size_t)zb * sBb + (size_t)zk * sBk + (size_t)(blockIdx.x * 128) * ldb;
    const size_t cOff = (size_t)zb * sCb + (size_t)zk * sCk
                      + (size_t)(blockIdx.y * 128) * ldc + (size_t)(blockIdx.x * 128);

    const int numK = Kdim >> 6;

    float c[4][4][4];
#pragma unroll
    for (int i = 0; i < 4; i++)
#pragma unroll
        for (int j = 0; j < 4; j++)
#pragma unroll
            for (int r = 0; r < 4; r++) c[i][j][r] = 0.0f;

    const int rlA = lane & 15;
    const int hiA = lane >> 4;
    const int rlB = ((lane >> 4) << 3) + (lane & 7);
    const int hiB = (lane >> 3) & 1;

    load_tile_h(smb,          Ab, lda, tid);
    load_tile_h(smb + TILEB,  Bb, ldb, tid);
    CP_COMMIT();
    if (numK > 1) {
        load_tile_h(smb + STAGEB,         Ab + BK, lda, tid);
        load_tile_h(smb + STAGEB + TILEB, Bb + BK, ldb, tid);
    }
    CP_COMMIT();

    int buf = 0;
    for (int kt = 0; kt < numK; kt++) {
        CP_WAIT1();
        __syncthreads();

        const int nk = kt + 2;
        if (nk < numK) {
            int nbuf = buf + 2; if (nbuf >= NSTAGE) nbuf -= NSTAGE;
            const uint32_t nbb = smb + nbuf * STAGEB;
            load_tile_h(nbb,         Ab + nk * BK, lda, tid);
            load_tile_h(nbb + TILEB, Bb + nk * BK, ldb, tid);
        }
        CP_COMMIT();

        const uint32_t At = smb + buf * STAGEB;
        const uint32_t Bt = At + TILEB;

#pragma unroll
        for (int kk = 0; kk < 4; kk++) {
            uint32_t a[4][4], bb[2][4];
            const int cA = kk * 2 + hiA;
            const int cB = kk * 2 + hiB;
#pragma unroll
            for (int i = 0; i < 4; i++) {
                const int row = warpMoff + i * 16 + rlA;
                uint32_t ad = At + ((uint32_t)row << 7)
                            + (uint32_t)(((cA ^ (row & 7)) << 4));
                LDSM4(a[i], ad);
            }
#pragma unroll
            for (int j = 0; j < 2; j++) {
                const int row = warpNoff + j * 16 + rlB;
                uint32_t bd = Bt + ((uint32_t)row << 7)
                            + (uint32_t)(((cB ^ (row & 7)) << 4));
                LDSM4(bb[j], bd);
            }
#pragma unroll
            for (int i = 0; i < 4; i++)
#pragma unroll
                for (int jj = 0; jj < 4; jj++)
                    mma_f16(c[i][jj], a[i], bb[jj >> 1][(jj & 1) * 2],
                                             bb[jj >> 1][(jj & 1) * 2 + 1]);
        }

        if (++buf == NSTAGE) buf = 0;
    }

    if (halfOut) {
        __half* Cb = (__half*)Cv + cOff;
#pragma unroll
        for (int i = 0; i < 4; i++) {
            const int r0 = warpMoff + i * 16 + gid;
#pragma unroll
            for (int jj = 0; jj < 4; jj++) {
                const int cc = warpNoff + jj * 8 + tg * 2;
                *(__half2*)(Cb + (size_t)r0 * ldc + cc) =
                    __floats2half2_rn(alpha * c[i][jj][0], alpha * c[i][jj][1]);
                *(__half2*)(Cb + (size_t)(r0 + 8) * ldc + cc) =
                    __floats2half2_rn(alpha * c[i][jj][2], alpha * c[i][jj][3]);
            }
        }
    } else {
        float* Cb = (float*)Cv + cOff;
#pragma unroll
        for (int i = 0; i < 4; i++) {
            const int r0 = warpMoff + i * 16 + gid;
#pragma unroll
            for (int jj = 0; jj < 4; jj++) {
                const int cc = warpNoff + jj * 8 + tg * 2;
                float2 v0, v1;
                v0.x = alpha * c[i][jj][0]; v0.y = alpha * c[i][jj][1];
                v1.x = alpha * c[i][jj][2]; v1.y = alpha * c[i][jj][3];
                *(float2*)(Cb + (size_t)r0 * ldc + cc)       = v0;
                *(float2*)(Cb + (size_t)(r0 + 8) * ldc + cc) = v1;
            }
        }
    }
}

// ============================================================================
// prep_x: one pass over xsa -> xh (fp16, same layout) AND xth (fp16, transposed)
// grid (32 l-tiles, 16 e-tiles, 4 batches), block (32,8)
// ============================================================================
__global__ void prep_x(const float* __restrict__ in,
                       __half* __restrict__ xh, __half* __restrict__ xth)
{
    __shared__ __half t[32][33];
    const int b = blockIdx.z;
    const int l0 = blockIdx.x * 32, e0 = blockIdx.y * 32;
    in  += (size_t)b * 524288;
    xh  += (size_t)b * 524288;
    xth += (size_t)b * 524288;
    const int x = threadIdx.x, y = threadIdx.y;  // 32 x 8
#pragma unroll
    for (int i = 0; i < 32; i += 8) {
        __half h = __float2half_rn(in[(size_t)(l0 + y + i) * 512 + e0 + x]);
        xh[(size_t)(l0 + y + i) * 512 + e0 + x] = h;
        t[y + i][x] = h;
    }
    __syncthreads();
#pragma unroll
    for (int i = 0; i < 32; i += 8)
        xth[(size_t)(e0 + y + i) * 1024 + l0 + x] = t[x][y + i];
}

// cvt_w: Wq f32 -> fp16
__global__ void cvt_w(const float* __restrict__ in, __half* __restrict__ out)
{
    int i = blockIdx.x * blockDim.x + threadIdx.x;   // 0..524287 (float4s)
    float4 v = ((const float4*)in)[i];
    ((__half2*)out)[2 * i]     = __floats2half2_rn(v.x, v.y);
    ((__half2*)out)[2 * i + 1] = __floats2half2_rn(v.z, v.w);
}

// ============================================================================
// softmax rows of 1024, in place (f32); also writes fp16 copy to ph
// ============================================================================
__global__ void softmax_rows_kernel(float* __restrict__ p, __half* __restrict__ ph)
{
    __shared__ float red[32];
    const size_t roff = (size_t)blockIdx.x * 1024;
    float* row = p + roff;
    const int t = threadIdx.x;

    float4 v = ((const float4*)row)[t];

    float m = fmaxf(fmaxf(v.x, v.y), fmaxf(v.z, v.w));
#pragma unroll
    for (int o = 16; o; o >>= 1) m = fmaxf(m, __shfl_xor_sync(0xffffffffu, m, o));
    if ((t & 31) == 0) red[t >> 5] = m;
    __syncthreads();
    if (t < 32) {
        float mm = (t < 8) ? red[t] : -CUDART_INF_F;
#pragma unroll
        for (int o = 4; o; o >>= 1) mm = fmaxf(mm, __shfl_xor_sync(0xffffffffu, mm, o));
        if (t == 0) red[0] = mm;
    }
    __syncthreads();
    m = red[0];
    __syncthreads();

    v.x = __expf(v.x - m); v.y = __expf(v.y - m);
    v.z = __expf(v.z - m); v.w = __expf(v.w - m);

    float s = v.x + v.y + v.z + v.w;
#pragma unroll
    for (int o = 16; o; o >>= 1) s += __shfl_xor_sync(0xffffffffu, s, o);
    if ((t & 31) == 0) red[t >> 5] = s;
    __syncthreads();
    if (t < 32) {
        float ss = (t < 8) ? red[t] : 0.0f;
#pragma unroll
        for (int o = 4; o; o >>= 1) ss += __shfl_xor_sync(0xffffffffu, ss, o);
        if (t == 0) red[0] = ss;
    }
    __syncthreads();
    const float inv = 1.0f / red[0];

    v.x *= inv; v.y *= inv; v.z *= inv; v.w *= inv;
    ((float4*)row)[t] = v;

    __half2* pp = (__half2*)(ph + roff);
    pp[2 * t]     = __floats2half2_rn(v.x, v.y);
    pp[2 * t + 1] = __floats2half2_rn(v.z, v.w);
}

// ============================================================================
extern "C" void kernel_launch(void* const* d_in, const int* in_sizes, int n_in,
                              void* d_out, int out_size)
{
    (void)in_sizes; (void)n_in; (void)out_size;
    const float* xsa = (const float*)d_in[0];
    const float* Wq  = (const float*)d_in[1];
    float* out  = (float*)d_out;
    float* xid  = out;
    float* pijk = out + 16777216UL;

    __half *qh, *xh, *wh, *xth, *ph;
    cudaGetSymbolAddress((void**)&qh,  g_qh);
    cudaGetSymbolAddress((void**)&xh,  g_xh);
    cudaGetSymbolAddress((void**)&wh,  g_wh);
    cudaGetSymbolAddress((void**)&xth, g_xth);
    cudaGetSymbolAddress((void**)&ph,  g_ph);

    cudaFuncSetAttribute(gemm_h, cudaFuncAttributeMaxDynamicSharedMemorySize, DSMEMB);

    const float inv_sqrt_e = 0.044194173824159216f;

    // prep: one pass over xsa (xh + xth), one over Wq (wh)
    prep_x<<<dim3(32, 16, 4), dim3(32, 8)>>>(xsa, xh, xth);
    cvt_w<<<2048, 256>>>(Wq, wh);

    // K1: q = xh @ wh^T   M=4096 N=4096 K=512, fp16 out
    gemm_h<<<dim3(32, 32, 1), NTHREADS, DSMEMB>>>(
        xh, 512, 0, 0,
        wh, 512, 0, 0,
        qh, 4096, 0, 0,
        512, 1.0f, 1, 1);

    // K2: logits = qh_bk @ xh_b^T / sqrt(E)   M=1024 N=1024 K=512, 32 batches
    gemm_h<<<dim3(8, 8, 32), NTHREADS, DSMEMB>>>(
        qh, 4096, 4194304L, 512L,
        xh, 512,  524288L,  0L,
        pijk, 8192, 8388608L, 1024L,
        512, inv_sqrt_e, 8, 0);

    // K3: softmax -> pijk f32 (output) + ph fp16 (K4 operand)
    softmax_rows_kernel<<<32768, 256>>>(pijk, ph);

    // K4: y = ph_bk @ xth_b^T   M=1024 N=512 K=1024, 32 batches
    // ph layout (b,l,k,m): row stride 8192, k stride 1024
    gemm_h<<<dim3(4, 8, 32), NTHREADS, DSMEMB>>>(
        ph,  8192, 8388608L, 1024L,
        xth, 1024, 524288L,  0L,
        xid, 4096, 4194304L, 512L,
        1024, 1.0f, 8, 0);
}

// round 13
// speedup vs baseline: 1.3525x; 1.0158x over previous
#include <cuda_runtime.h>
#include <cuda_fp16.h>
#include <cstdint>
#include <math_constants.h>

// ============================================================================
// QKV_Attention via mma.sync m16n8k16 fp16 (f32 acc) + ldmatrix.
// Round 13: R12 champion + PDL (programmatic dependent launch).
// Every kernel: griddepcontrol.wait at entry (also guards against cross-replay
// races in the replayed graph), launch_dependents after final stores.
// Every launch: cudaLaunchKernelEx + programmaticStreamSerialization.
// ============================================================================

#define NTHREADS 256
#define BK 64
#define TILEB 16384                 // 128 rows x 128B
#define STAGEB (2*TILEB)            // A + B
#define NSTAGE 3
#define DSMEMB (NSTAGE*STAGEB)      // 98304

__device__ __half g_qh [4096UL*4096UL];      // 32 MB
__device__ __half g_xh [4UL*1024UL*512UL];   //  4 MB
__device__ __half g_wh [4096UL*512UL];       //  4 MB
__device__ __half g_xth[4UL*512UL*1024UL];   //  4 MB
__device__ __half g_ph [32768UL*1024UL];     // 64 MB

// ---------------------------------------------------------------- helpers
#define GDC_WAIT()   asm volatile("griddepcontrol.wait;" ::: "memory")
#define GDC_LAUNCH() asm volatile("griddepcontrol.launch_dependents;" ::: "memory")

__device__ __forceinline__ uint32_t smem_u32(const void* p) {
    uint32_t a;
    asm("{ .reg .u64 t; cvta.to.shared.u64 t, %1; cvt.u32.u64 %0, t; }"
        : "=r"(a) : "l"(p));
    return a;
}
#define CP16(d, s) \
    asm volatile("cp.async.cg.shared.global [%0], [%1], 16;" :: "r"(d), "l"(s))
#define CP_COMMIT() asm volatile("cp.async.commit_group;" ::: "memory")
#define CP_WAIT1()  asm volatile("cp.async.wait_group 1;" ::: "memory")

#define LDSM4(r, a) \
    asm volatile("ldmatrix.sync.aligned.m8n8.x4.shared.b16 {%0,%1,%2,%3}, [%4];" \
        : "=r"((r)[0]), "=r"((r)[1]), "=r"((r)[2]), "=r"((r)[3]) : "r"(a))

__device__ __forceinline__ void mma_f16(float c[4], const uint32_t a[4],
                                        uint32_t b0, uint32_t b1) {
    asm volatile(
        "mma.sync.aligned.m16n8k16.row.col.f32.f16.f16.f32 "
        "{%0,%1,%2,%3}, {%4,%5,%6,%7}, {%8,%9}, {%0,%1,%2,%3};"
        : "+f"(c[0]), "+f"(c[1]), "+f"(c[2]), "+f"(c[3])
        : "r"(a[0]), "r"(a[1]), "r"(a[2]), "r"(a[3]), "r"(b0), "r"(b1));
}

// load 128 rows x 64 fp16 (row stride ld elems) into XOR-swizzled smem tile
__device__ __forceinline__ void load_tile_h(uint32_t dst, const __half* g, int ld, int tid) {
#pragma unroll
    for (int i = 0; i < 4; i++) {
        int idx = tid + i * NTHREADS;
        int row = idx >> 3;
        int c   = idx & 7;
        uint32_t off = (uint32_t)(row << 7) | (uint32_t)(((c ^ (row & 7)) << 4));
        CP16(dst + off, g + (size_t)row * ld + (c << 3));
    }
}

// ============================================================================
// NT GEMM (fp16 in, f32 acc): C[m,n] = alpha * sum_k A[m,k]*B[n,k]
// CTA tile 128x128, 8 warps (2x4), warp tile 64x32, BK=64, 3 stages.
// (compute core byte-identical to round-6/12 champion)
// ============================================================================
__global__ void __launch_bounds__(NTHREADS, 2)
gemm_h(const __half* __restrict__ A, int lda, long sAb, long sAk,
       const __half* __restrict__ B, int ldb, long sBb, long sBk,
       void* __restrict__ Cv, int ldc, long sCb, long sCk,
       int Kdim, float alpha, int Kcnt, int halfOut)
{
    extern __shared__ __half smh[];
    const uint32_t smb = smem_u32(smh);

    const int tid  = threadIdx.x;
    const int wid  = tid >> 5;
    const int lane = tid & 31;
    const int gid  = lane >> 2;
    const int tg   = lane & 3;
    const int warpMoff = (wid >> 2) * 64;
    const int warpNoff = (wid & 3) * 32;

    const int z  = blockIdx.z;
    const int zb = z / Kcnt;
    const int zk = z - zb * Kcnt;
    const __half* Ab = A + (size_t)zb * sAb + (size_t)zk * sAk + (size_t)(blockIdx.y * 128) * lda;
    const __half* Bb = B + (size_t)zb * sBb + (size_t)zk * sBk + (size_t)(blockIdx.x * 128) * ldb;
    const size_t cOff = (size_t)zb * sCb + (size_t)zk * sCk
                      + (size_t)(blockIdx.y * 128) * ldc + (size_t)(blockIdx.x * 128);

    const int numK = Kdim >> 6;

    float c[4][4][4];
#pragma unroll
    for (int i = 0; i < 4; i++)
#pragma unroll
        for (int j = 0; j < 4; j++)
#pragma unroll
            for (int r = 0; r < 4; r++) c[i][j][r] = 0.0f;

    const int rlA = lane & 15;
    const int hiA = lane >> 4;
    const int rlB = ((lane >> 4) << 3) + (lane & 7);
    const int hiB = (lane >> 3) & 1;

    GDC_WAIT();   // predecessor's writes (A/B producers) visible from here

    load_tile_h(smb,          Ab, lda, tid);
    load_tile_h(smb + TILEB,  Bb, ldb, tid);
    CP_COMMIT();
    if (numK > 1) {
        load_tile_h(smb + STAGEB,         Ab + BK, lda, tid);
        load_tile_h(smb + STAGEB + TILEB, Bb + BK, ldb, tid);
    }
    CP_COMMIT();

    int buf = 0;
    for (int kt = 0; kt < numK; kt++) {
        CP_WAIT1();
        __syncthreads();

        const int nk = kt + 2;
        if (nk < numK) {
            int nbuf = buf + 2; if (nbuf >= NSTAGE) nbuf -= NSTAGE;
            const uint32_t nbb = smb + nbuf * STAGEB;
            load_tile_h(nbb,         Ab + nk * BK, lda, tid);
            load_tile_h(nbb + TILEB, Bb + nk * BK, ldb, tid);
        }
        CP_COMMIT();

        const uint32_t At = smb + buf * STAGEB;
        const uint32_t Bt = At + TILEB;

#pragma unroll
        for (int kk = 0; kk < 4; kk++) {
            uint32_t a[4][4], bb[2][4];
            const int cA = kk * 2 + hiA;
            const int cB = kk * 2 + hiB;
#pragma unroll
            for (int i = 0; i < 4; i++) {
                const int row = warpMoff + i * 16 + rlA;
                uint32_t ad = At + ((uint32_t)row << 7)
                            + (uint32_t)(((cA ^ (row & 7)) << 4));
                LDSM4(a[i], ad);
            }
#pragma unroll
            for (int j = 0; j < 2; j++) {
                const int row = warpNoff + j * 16 + rlB;
                uint32_t bd = Bt + ((uint32_t)row << 7)
                            + (uint32_t)(((cB ^ (row & 7)) << 4));
                LDSM4(bb[j], bd);
            }
#pragma unroll
            for (int i = 0; i < 4; i++)
#pragma unroll
                for (int jj = 0; jj < 4; jj++)
                    mma_f16(c[i][jj], a[i], bb[jj >> 1][(jj & 1) * 2],
                                             bb[jj >> 1][(jj & 1) * 2 + 1]);
        }

        if (++buf == NSTAGE) buf = 0;
    }

    if (halfOut) {
        __half* Cb = (__half*)Cv + cOff;
#pragma unroll
        for (int i = 0; i < 4; i++) {
            const int r0 = warpMoff + i * 16 + gid;
#pragma unroll
            for (int jj = 0; jj < 4; jj++) {
                const int cc = warpNoff + jj * 8 + tg * 2;
                *(__half2*)(Cb + (size_t)r0 * ldc + cc) =
                    __floats2half2_rn(alpha * c[i][jj][0], alpha * c[i][jj][1]);
                *(__half2*)(Cb + (size_t)(r0 + 8) * ldc + cc) =
                    __floats2half2_rn(alpha * c[i][jj][2], alpha * c[i][jj][3]);
            }
        }
    } else {
        float* Cb = (float*)Cv + cOff;
#pragma unroll
        for (int i = 0; i < 4; i++) {
            const int r0 = warpMoff + i * 16 + gid;
#pragma unroll
            for (int jj = 0; jj < 4; jj++) {
                const int cc = warpNoff + jj * 8 + tg * 2;
                float2 v0, v1;
                v0.x = alpha * c[i][jj][0]; v0.y = alpha * c[i][jj][1];
                v1.x = alpha * c[i][jj][2]; v1.y = alpha * c[i][jj][3];
                *(float2*)(Cb + (size_t)r0 * ldc + cc)       = v0;
                *(float2*)(Cb + (size_t)(r0 + 8) * ldc + cc) = v1;
            }
        }
    }
    GDC_LAUNCH();   // stores above are visible to the dependent grid
}

// ============================================================================
// prep_x: one pass over xsa -> xh (fp16) AND xth (fp16 transposed)
// ============================================================================
__global__ void prep_x(const float* __restrict__ in,
                       __half* __restrict__ xh, __half* __restrict__ xth)
{
    __shared__ __half t[32][33];
    const int b = blockIdx.z;
    const int l0 = blockIdx.x * 32, e0 = blockIdx.y * 32;
    in  += (size_t)b * 524288;
    xh  += (size_t)b * 524288;
    xth += (size_t)b * 524288;
    const int x = threadIdx.x, y = threadIdx.y;
    GDC_WAIT();   // previous graph REPLAY's K4 still reads xth without this
#pragma unroll
    for (int i = 0; i < 32; i += 8) {
        __half h = __float2half_rn(in[(size_t)(l0 + y + i) * 512 + e0 + x]);
        xh[(size_t)(l0 + y + i) * 512 + e0 + x] = h;
        t[y + i][x] = h;
    }
    __syncthreads();
#pragma unroll
    for (int i = 0; i < 32; i += 8)
        xth[(size_t)(e0 + y + i) * 1024 + l0 + x] = t[x][y + i];
    GDC_LAUNCH();
}

// cvt_w: Wq f32 -> fp16
__global__ void cvt_w(const float* __restrict__ in, __half* __restrict__ out)
{
    int i = blockIdx.x * blockDim.x + threadIdx.x;
    GDC_WAIT();
    float4 v = ((const float4*)in)[i];
    ((__half2*)out)[2 * i]     = __floats2half2_rn(v.x, v.y);
    ((__half2*)out)[2 * i + 1] = __floats2half2_rn(v.z, v.w);
    GDC_LAUNCH();
}

// ============================================================================
// softmax rows of 1024, in place (f32); also writes fp16 copy to ph
// ============================================================================
__global__ void softmax_rows_kernel(float* __restrict__ p, __half* __restrict__ ph)
{
    __shared__ float red[32];
    const size_t roff = (size_t)blockIdx.x * 1024;
    float* row = p + roff;
    const int t = threadIdx.x;

    GDC_WAIT();   // K2's pijk writes visible from here

    float4 v = ((const float4*)row)[t];

    float m = fmaxf(fmaxf(v.x, v.y), fmaxf(v.z, v.w));
#pragma unroll
    for (int o = 16; o; o >>= 1) m = fmaxf(m, __shfl_xor_sync(0xffffffffu, m, o));
    if ((t & 31) == 0) red[t >> 5] = m;
    __syncthreads();
    if (t < 32) {
        float mm = (t < 8) ? red[t] : -CUDART_INF_F;
#pragma unroll
        for (int o = 4; o; o >>= 1) mm = fmaxf(mm, __shfl_xor_sync(0xffffffffu, mm, o));
        if (t == 0) red[0] = mm;
    }
    __syncthreads();
    m = red[0];
    __syncthreads();

    v.x = __expf(v.x - m); v.y = __expf(v.y - m);
    v.z = __expf(v.z - m); v.w = __expf(v.w - m);

    float s = v.x + v.y + v.z + v.w;
#pragma unroll
    for (int o = 16; o; o >>= 1) s += __shfl_xor_sync(0xffffffffu, s, o);
    if ((t & 31) == 0) red[t >> 5] = s;
    __syncthreads();
    if (t < 32) {
        float ss = (t < 8) ? red[t] : 0.0f;
#pragma unroll
        for (int o = 4; o; o >>= 1) ss += __shfl_xor_sync(0xffffffffu, ss, o);
        if (t == 0) red[0] = ss;
    }
    __syncthreads();
    const float inv = 1.0f / red[0];

    v.x *= inv; v.y *= inv; v.z *= inv; v.w *= inv;
    ((float4*)row)[t] = v;

    __half2* pp = (__half2*)(ph + roff);
    pp[2 * t]     = __floats2half2_rn(v.x, v.y);
    pp[2 * t + 1] = __floats2half2_rn(v.z, v.w);
    GDC_LAUNCH();
}

// ============================================================================
extern "C" void kernel_launch(void* const* d_in, const int* in_sizes, int n_in,
                              void* d_out, int out_size)
{
    (void)in_sizes; (void)n_in; (void)out_size;
    const float* xsa = (const float*)d_in[0];
    const float* Wq  = (const float*)d_in[1];
    float* out  = (float*)d_out;
    float* xid  = out;
    float* pijk = out + 16777216UL;

    __half *qh, *xh, *wh, *xth, *ph;
    cudaGetSymbolAddress((void**)&qh,  g_qh);
    cudaGetSymbolAddress((void**)&xh,  g_xh);
    cudaGetSymbolAddress((void**)&wh,  g_wh);
    cudaGetSymbolAddress((void**)&xth, g_xth);
    cudaGetSymbolAddress((void**)&ph,  g_ph);

    cudaFuncSetAttribute(gemm_h, cudaFuncAttributeMaxDynamicSharedMemorySize, DSMEMB);

    const float inv_sqrt_e = 0.044194173824159216f;

    // PDL launch config: every kernel may launch while its predecessor drains;
    // each kernel gates itself with griddepcontrol.wait.
    cudaLaunchAttribute at[1];
    at[0].id = cudaLaunchAttributeProgrammaticStreamSerialization;
    at[0].val.programmaticStreamSerializationAllowed = 1;

    cudaLaunchConfig_t cfg{};
    cfg.attrs = at;
    cfg.numAttrs = 1;
    cfg.stream = 0;

    // prep_x
    cfg.gridDim = dim3(32, 16, 4); cfg.blockDim = dim3(32, 8); cfg.dynamicSmemBytes = 0;
    cudaLaunchKernelEx(&cfg, prep_x, xsa, xh, xth);

    // cvt_w
    cfg.gridDim = dim3(2048); cfg.blockDim = dim3(256); cfg.dynamicSmemBytes = 0;
    cudaLaunchKernelEx(&cfg, cvt_w, Wq, wh);

    // K1: q = xh @ wh^T   M=4096 N=4096 K=512, fp16 out
    cfg.gridDim = dim3(32, 32, 1); cfg.blockDim = dim3(NTHREADS); cfg.dynamicSmemBytes = DSMEMB;
    cudaLaunchKernelEx(&cfg, gemm_h,
        (const __half*)xh, 512, 0L, 0L,
        (const __half*)wh, 512, 0L, 0L,
        (void*)qh, 4096, 0L, 0L,
        512, 1.0f, 1, 1);

    // K2: logits = qh_bk @ xh_b^T / sqrt(E)   M=1024 N=1024 K=512, 32 batches
    cfg.gridDim = dim3(8, 8, 32);
    cudaLaunchKernelEx(&cfg, gemm_h,
        (const __half*)qh, 4096, 4194304L, 512L,
        (const __half*)xh, 512,  524288L,  0L,
        (void*)pijk, 8192, 8388608L, 1024L,
        512, inv_sqrt_e, 8, 0);

    // K3: softmax -> pijk f32 (output) + ph fp16 (K4 operand)
    cfg.gridDim = dim3(32768); cfg.blockDim = dim3(256); cfg.dynamicSmemBytes = 0;
    cudaLaunchKernelEx(&cfg, softmax_rows_kernel, pijk, ph);

    // K4: y = ph_bk @ xth_b^T   M=1024 N=512 K=1024, 32 batches
    cfg.gridDim = dim3(4, 8, 32); cfg.blockDim = dim3(NTHREADS); cfg.dynamicSmemBytes = DSMEMB;
    cudaLaunchKernelEx(&cfg, gemm_h,
        (const __half*)ph,  8192, 8388608L, 1024L,
        (const __half*)xth, 1024, 524288L,  0L,
        (void*)xid, 4096, 4194304L, 512L,
        1024, 1.0f, 8, 0);
}